// round 1
// baseline (speedup 1.0000x reference)
#include <cuda_runtime.h>
#include <math.h>

// Problem constants
#define NNEG (-1e9f)
constexpr int THREADS = 512;
constexpr int WARPS   = THREADS / 32;

// Shared memory layout (float offsets)
constexpr int OFF_W    = 0;                 // 64*64  = 4096
constexpr int OFF_AS   = OFF_W + 4096;      // 64
constexpr int OFF_AD   = OFF_AS + 64;       // 64
constexpr int OFF_WX   = OFF_AD + 64;       // 40*192 = 7680
constexpr int OFF_WHG  = OFF_WX + 7680;     // 64*192 = 12288
constexpr int OFF_B    = OFF_WHG + 12288;   // 192
constexpr int OFF_SCR  = OFF_B + 192;       // 24384
constexpr int SCR_PER_WARP = 1088;          // per-warp scratch: ch/attn [0..1023], x [256..295], pooled [512..575]
constexpr int SMEM_FLOATS = OFF_SCR + WARPS * SCR_PER_WARP;  // 41792 floats = 167168 B

__global__ __launch_bounds__(THREADS, 1)
void rann_kernel(const float* __restrict__ xf,       // [N,40]
                 const float* __restrict__ ch,       // [N,16,64]
                 const float* __restrict__ Ac,       // [N,16,16]
                 const int*   __restrict__ ccnt,     // [N]
                 const float* __restrict__ gW,       // [64,64]
                 const float* __restrict__ gAs,      // [64]
                 const float* __restrict__ gAd,      // [64]
                 const float* __restrict__ gWx,      // [40,192]
                 const float* __restrict__ gWhg,     // [64,192]
                 const float* __restrict__ gB,       // [192]
                 float* __restrict__ out,            // [N,64]
                 int N)
{
    extern __shared__ float sm[];
    float* sW   = sm + OFF_W;
    float* sAs  = sm + OFF_AS;
    float* sAd  = sm + OFF_AD;
    float* sWx  = sm + OFF_WX;
    float* sWhg = sm + OFF_WHG;
    float* sB   = sm + OFF_B;

    const int tid = threadIdx.x;

    // Stage weights into shared once per block (persistent block)
    for (int i = tid; i < 4096;  i += THREADS) sW[i]   = gW[i];
    for (int i = tid; i < 64;    i += THREADS) { sAs[i] = gAs[i]; sAd[i] = gAd[i]; }
    for (int i = tid; i < 7680;  i += THREADS) sWx[i]  = gWx[i];
    for (int i = tid; i < 12288; i += THREADS) sWhg[i] = gWhg[i];
    if (tid < 192) sB[tid] = gB[tid];
    __syncthreads();

    const int warp = tid >> 5;
    const int lane = tid & 31;
    float* scr = sm + OFF_SCR + warp * SCR_PER_WARP;
    float4* scr4 = (float4*)scr;

    for (int node = blockIdx.x * WARPS + warp; node < N; node += gridDim.x * WARPS) {
        // ---- Load child_hiddens tile [16][64] into per-warp scratch ----
        const float4* chg = (const float4*)(ch + (size_t)node * 1024);
        #pragma unroll
        for (int i = 0; i < 8; i++) scr4[lane + 32 * i] = chg[lane + 32 * i];
        __syncwarp();

        // ---- Wh = ch @ W : lane holds columns k = lane, lane+32, all 16 rows ----
        float acc0[16], acc1[16];
        #pragma unroll
        for (int c = 0; c < 16; c++) { acc0[c] = 0.f; acc1[c] = 0.f; }

        #pragma unroll 1
        for (int h4 = 0; h4 < 16; h4++) {
            const int h = h4 * 4;
            float w0x = sW[(h + 0) * 64 + lane];
            float w0y = sW[(h + 1) * 64 + lane];
            float w0z = sW[(h + 2) * 64 + lane];
            float w0w = sW[(h + 3) * 64 + lane];
            float w1x = sW[(h + 0) * 64 + lane + 32];
            float w1y = sW[(h + 1) * 64 + lane + 32];
            float w1z = sW[(h + 2) * 64 + lane + 32];
            float w1w = sW[(h + 3) * 64 + lane + 32];
            #pragma unroll
            for (int c = 0; c < 16; c++) {
                float4 q = scr4[c * 16 + h4];   // broadcast
                acc0[c] = fmaf(q.x, w0x, fmaf(q.y, w0y, fmaf(q.z, w0z, fmaf(q.w, w0w, acc0[c]))));
                acc1[c] = fmaf(q.x, w1x, fmaf(q.y, w1y, fmaf(q.z, w1z, fmaf(q.w, w1w, acc1[c]))));
            }
        }

        // ---- src[c] = Wh[c]·a_src, dst[c] = Wh[c]·a_dst (warp reduce over k) ----
        float sv0 = sAs[lane], sv1 = sAs[lane + 32];
        float dv0 = sAd[lane], dv1 = sAd[lane + 32];
        float sp[16], dp[16];
        #pragma unroll
        for (int c = 0; c < 16; c++) {
            sp[c] = fmaf(acc0[c], sv0, acc1[c] * sv1);
            dp[c] = fmaf(acc0[c], dv0, acc1[c] * dv1);
        }
        #pragma unroll
        for (int off = 16; off > 0; off >>= 1) {
            #pragma unroll
            for (int c = 0; c < 16; c++) {
                sp[c] += __shfl_xor_sync(0xffffffffu, sp[c], off);
                dp[c] += __shfl_xor_sync(0xffffffffu, dp[c], off);
            }
        }

        const int cc = ccnt[node];

        // ---- Attention row softmax: lane handles row ai = lane>>1, j in [jb, jb+8) ----
        const int ai = lane >> 1;
        const int jb = (lane & 1) * 8;
        const float* Arow = Ac + (size_t)node * 256 + ai * 16 + jb;
        float4 Aq0 = *(const float4*)(Arow);
        float4 Aq1 = *(const float4*)(Arow + 4);
        float av[8] = {Aq0.x, Aq0.y, Aq0.z, Aq0.w, Aq1.x, Aq1.y, Aq1.z, Aq1.w};
        const bool vi = ai < cc;
        float ev[8];
        #pragma unroll
        for (int jj = 0; jj < 8; jj++) {
            int j = jb + jj;
            bool m = vi && (j < cc) && (av[jj] > 0.5f);
            float e = sp[ai] + dp[j];
            e = (e >= 0.f) ? e : 0.2f * e;       // leaky_relu 0.2
            ev[jj] = m ? e : NNEG;
        }
        float mx = ev[0];
        #pragma unroll
        for (int jj = 1; jj < 8; jj++) mx = fmaxf(mx, ev[jj]);
        mx = fmaxf(mx, __shfl_xor_sync(0xffffffffu, mx, 1));
        float p[8], s = 0.f;
        #pragma unroll
        for (int jj = 0; jj < 8; jj++) { p[jj] = __expf(ev[jj] - mx); s += p[jj]; }
        s += __shfl_xor_sync(0xffffffffu, s, 1);
        float inv = 1.f / s;

        __syncwarp();  // all lanes done reading ch tile before attn overwrites scratch
        #pragma unroll
        for (int jj = 0; jj < 8; jj++) scr[ai * 16 + jb + jj] = p[jj] * inv;
        __syncwarp();

        // ---- h_msg[i] = attn[i] @ Wh ; elu ; masked maxpool over valid rows ----
        float pool0 = NNEG, pool1 = NNEG;
        #pragma unroll 1
        for (int i2 = 0; i2 < cc; i2++) {
            float m0 = 0.f, m1 = 0.f;
            #pragma unroll
            for (int j4 = 0; j4 < 4; j4++) {
                float4 aq = scr4[i2 * 4 + j4];   // broadcast attn row chunk
                m0 = fmaf(aq.x, acc0[j4 * 4 + 0], fmaf(aq.y, acc0[j4 * 4 + 1],
                     fmaf(aq.z, acc0[j4 * 4 + 2], fmaf(aq.w, acc0[j4 * 4 + 3], m0))));
                m1 = fmaf(aq.x, acc1[j4 * 4 + 0], fmaf(aq.y, acc1[j4 * 4 + 1],
                     fmaf(aq.z, acc1[j4 * 4 + 2], fmaf(aq.w, acc1[j4 * 4 + 3], m1))));
            }
            m0 = (m0 > 0.f) ? m0 : expm1f(m0);   // elu
            m1 = (m1 > 0.f) ? m1 : expm1f(m1);
            pool0 = fmaxf(pool0, m0);
            pool1 = fmaxf(pool1, m1);
        }

        // ---- GRU: gx = x@Wx + b (keep gx, gh separate for the n-gate) ----
        for (int i = lane; i < 40; i += 32) scr[256 + i] = xf[(size_t)node * 40 + i];
        scr[512 + lane] = pool0;
        scr[544 + lane] = pool1;
        __syncwarp();

        float gx[6], gh[6];
        #pragma unroll
        for (int m = 0; m < 6; m++) { gx[m] = sB[lane + 32 * m]; gh[m] = 0.f; }

        #pragma unroll 1
        for (int d = 0; d < 40; d++) {
            float xv = scr[256 + d];
            const float* wrow = sWx + d * 192 + lane;
            #pragma unroll
            for (int m = 0; m < 6; m++) gx[m] = fmaf(xv, wrow[32 * m], gx[m]);
        }
        #pragma unroll 1
        for (int k = 0; k < 64; k++) {
            float pv = scr[512 + k];
            const float* wrow = sWhg + k * 192 + lane;
            #pragma unroll
            for (int m = 0; m < 6; m++) gh[m] = fmaf(pv, wrow[32 * m], gh[m]);
        }

        float z0 = 1.f / (1.f + __expf(-(gx[0] + gh[0])));
        float z1 = 1.f / (1.f + __expf(-(gx[1] + gh[1])));
        float r0 = 1.f / (1.f + __expf(-(gx[2] + gh[2])));
        float r1 = 1.f / (1.f + __expf(-(gx[3] + gh[3])));
        float n0 = tanhf(fmaf(r0, gh[4], gx[4]));
        float n1 = tanhf(fmaf(r1, gh[5], gx[5]));

        out[(size_t)node * 64 + lane]      = (1.f - z0) * n0 + z0 * pool0;
        out[(size_t)node * 64 + lane + 32] = (1.f - z1) * n1 + z1 * pool1;

        __syncwarp();  // scratch reuse safety across node iterations
    }
}

extern "C" void kernel_launch(void* const* d_in, const int* in_sizes, int n_in,
                              void* d_out, int out_size) {
    const float* node_features = (const float*)d_in[0];
    const float* child_hiddens = (const float*)d_in[1];
    const float* A_c           = (const float*)d_in[2];
    const int*   child_count   = (const int*)  d_in[3];
    const float* W             = (const float*)d_in[4];
    const float* a_src         = (const float*)d_in[5];
    const float* a_dst         = (const float*)d_in[6];
    const float* Wx            = (const float*)d_in[7];
    const float* Wh_g          = (const float*)d_in[8];
    const float* b             = (const float*)d_in[9];
    float* out = (float*)d_out;
    const int N = in_sizes[3];

    int dev = 0;
    cudaGetDevice(&dev);
    int sms = 148;
    cudaDeviceGetAttribute(&sms, cudaDevAttrMultiProcessorCount, dev);

    const size_t smem_bytes = (size_t)SMEM_FLOATS * sizeof(float);
    cudaFuncSetAttribute(rann_kernel, cudaFuncAttributeMaxDynamicSharedMemorySize,
                         (int)smem_bytes);

    rann_kernel<<<sms, THREADS, smem_bytes>>>(node_features, child_hiddens, A_c,
                                              child_count, W, a_src, a_dst,
                                              Wx, Wh_g, b, out, N);
}

// round 11
// speedup vs baseline: 1.1108x; 1.1108x over previous
#include <cuda_runtime.h>
#include <math.h>

// Problem constants
#define NNEG (-1e9f)
constexpr int THREADS = 512;
constexpr int WARPS   = THREADS / 32;

// Shared memory layout (float offsets)
constexpr int OFF_W    = 0;                 // W row-major 64*64 = 4096
constexpr int OFF_U    = OFF_W + 4096;      // u = W@a_src [64]
constexpr int OFF_V    = OFF_U + 64;        // v = W@a_dst [64]
constexpr int OFF_WXT  = OFF_V + 64;        // Wx^T  [192 cols][44] = 8448
constexpr int OFF_WHGT = OFF_WXT + 8448;    // Whg^T [192 cols][68] = 13056
constexpr int OFF_B    = OFF_WHGT + 13056;  // 192
constexpr int OFF_SCR  = OFF_B + 192;       // 25920
// per-warp scratch: ch/attn [0..1023], dst [1024..1039], x [256..295], pooled [512..575]
constexpr int SCR_PER_WARP = 1088;
constexpr int SMEM_FLOATS = OFF_SCR + WARPS * SCR_PER_WARP;  // 43328 floats = 173312 B

__global__ __launch_bounds__(THREADS, 1)
void rann_kernel(const float* __restrict__ xf,       // [N,40]
                 const float* __restrict__ ch,       // [N,16,64]
                 const float* __restrict__ Ac,       // [N,16,16]
                 const int*   __restrict__ ccnt,     // [N]
                 const float* __restrict__ gW,       // [64,64]
                 const float* __restrict__ gAs,      // [64]
                 const float* __restrict__ gAd,      // [64]
                 const float* __restrict__ gWx,      // [40,192]
                 const float* __restrict__ gWhg,     // [64,192]
                 const float* __restrict__ gB,       // [192]
                 float* __restrict__ out,            // [N,64]
                 int N)
{
    extern __shared__ float sm[];
    float* sW    = sm + OFF_W;
    float* sU    = sm + OFF_U;
    float* sV    = sm + OFF_V;
    float* sWxT  = sm + OFF_WXT;
    float* sWhgT = sm + OFF_WHGT;
    float* sB    = sm + OFF_B;

    const int tid = threadIdx.x;

    // Stage weights into shared once per block (persistent block)
    for (int i = tid; i < 4096;  i += THREADS) sW[i] = gW[i];
    for (int i = tid; i < 7680;  i += THREADS) {           // Wx^T[col][d], stride 44
        int d = i / 192, col = i % 192;
        sWxT[col * 44 + d] = gWx[i];
    }
    for (int i = tid; i < 12288; i += THREADS) {           // Whg^T[col][k], stride 68
        int k = i / 192, col = i % 192;
        sWhgT[col * 68 + k] = gWhg[i];
    }
    if (tid < 128) {                                       // u = W@a_src, v = W@a_dst
        const float* av = (tid < 64) ? gAs : gAd;
        int h = tid & 63;
        float s = 0.f;
        #pragma unroll 8
        for (int k = 0; k < 64; k++) s = fmaf(gW[h * 64 + k], av[k], s);
        ((tid < 64) ? sU : sV)[h] = s;
    }
    if (tid < 192) sB[tid] = gB[tid];
    __syncthreads();

    const int warp = tid >> 5;
    const int lane = tid & 31;
    float* scr  = sm + OFF_SCR + warp * SCR_PER_WARP;
    float4* scr4 = (float4*)scr;
    float* scrD = scr + 1024;                    // dst[16]

    for (int node = blockIdx.x * WARPS + warp; node < N; node += gridDim.x * WARPS) {
        // ---- Load child_hiddens tile [16][64] into per-warp scratch ----
        const float4* chg = (const float4*)(ch + (size_t)node * 1024);
        #pragma unroll
        for (int i = 0; i < 8; i++) scr4[lane + 32 * i] = chg[lane + 32 * i];
        __syncwarp();

        // ---- Wh = ch @ W : lane holds columns k = lane, lane+32, all 16 rows ----
        float acc0[16], acc1[16];
        #pragma unroll
        for (int c = 0; c < 16; c++) { acc0[c] = 0.f; acc1[c] = 0.f; }

        #pragma unroll 1
        for (int h4 = 0; h4 < 16; h4++) {
            const int h = h4 * 4;
            float w0x = sW[(h + 0) * 64 + lane];
            float w0y = sW[(h + 1) * 64 + lane];
            float w0z = sW[(h + 2) * 64 + lane];
            float w0w = sW[(h + 3) * 64 + lane];
            float w1x = sW[(h + 0) * 64 + lane + 32];
            float w1y = sW[(h + 1) * 64 + lane + 32];
            float w1z = sW[(h + 2) * 64 + lane + 32];
            float w1w = sW[(h + 3) * 64 + lane + 32];
            #pragma unroll
            for (int c = 0; c < 16; c++) {
                float4 q = scr4[c * 16 + h4];   // broadcast
                acc0[c] = fmaf(q.x, w0x, fmaf(q.y, w0y, fmaf(q.z, w0z, fmaf(q.w, w0w, acc0[c]))));
                acc1[c] = fmaf(q.x, w1x, fmaf(q.y, w1y, fmaf(q.z, w1z, fmaf(q.w, w1w, acc1[c]))));
            }
        }

        const int cc = ccnt[node];
        const int ai = lane >> 1;            // attention row for this lane pair
        const int half = lane & 1;

        // ---- src[ai], dst[ai] via u,v: src[c] = sum_h ch[c][h]*u[h] ----
        {
            const float4* chrow = (const float4*)(scr + ai * 64 + half * 32);
            const float4* up    = (const float4*)(sU + half * 32);
            const float4* vp    = (const float4*)(sV + half * 32);
            float su = 0.f, sv = 0.f;
            #pragma unroll
            for (int q = 0; q < 8; q++) {
                float4 t = chrow[q], uq = up[q], vq = vp[q];
                su = fmaf(t.x, uq.x, fmaf(t.y, uq.y, fmaf(t.z, uq.z, fmaf(t.w, uq.w, su))));
                sv = fmaf(t.x, vq.x, fmaf(t.y, vq.y, fmaf(t.z, vq.z, fmaf(t.w, vq.w, sv))));
            }
            su += __shfl_xor_sync(0xffffffffu, su, 1);
            sv += __shfl_xor_sync(0xffffffffu, sv, 1);
            if (!half) scrD[ai] = sv;        // publish dst[c] for column reads
            __syncwarp();

            // ---- Attention row softmax: row ai, j in [jb, jb+8) ----
            const int jb = half * 8;
            const float* Arow = Ac + (size_t)node * 256 + ai * 16 + jb;
            float4 Aq0 = *(const float4*)(Arow);
            float4 Aq1 = *(const float4*)(Arow + 4);
            float av8[8] = {Aq0.x, Aq0.y, Aq0.z, Aq0.w, Aq1.x, Aq1.y, Aq1.z, Aq1.w};
            float4 d0 = *(const float4*)(scrD + jb);
            float4 d1 = *(const float4*)(scrD + jb + 4);
            float dv8[8] = {d0.x, d0.y, d0.z, d0.w, d1.x, d1.y, d1.z, d1.w};
            const bool vi = ai < cc;
            float ev[8];
            #pragma unroll
            for (int jj = 0; jj < 8; jj++) {
                int j = jb + jj;
                bool m = vi && (j < cc) && (av8[jj] > 0.5f);
                float e = su + dv8[jj];
                e = (e >= 0.f) ? e : 0.2f * e;       // leaky_relu 0.2
                ev[jj] = m ? e : NNEG;
            }
            float mx = ev[0];
            #pragma unroll
            for (int jj = 1; jj < 8; jj++) mx = fmaxf(mx, ev[jj]);
            mx = fmaxf(mx, __shfl_xor_sync(0xffffffffu, mx, 1));
            float p[8], s = 0.f;
            #pragma unroll
            for (int jj = 0; jj < 8; jj++) { p[jj] = __expf(ev[jj] - mx); s += p[jj]; }
            s += __shfl_xor_sync(0xffffffffu, s, 1);
            float inv = 1.f / s;

            __syncwarp();  // all lanes done reading ch tile before attn overwrites scratch
            #pragma unroll
            for (int jj = 0; jj < 8; jj++) scr[ai * 16 + jb + jj] = p[jj] * inv;
            __syncwarp();
        }

        // ---- h_msg[i] = attn[i] @ Wh ; elu ; masked maxpool over valid rows ----
        float pool0 = NNEG, pool1 = NNEG;
        #pragma unroll 1
        for (int i2 = 0; i2 < cc; i2++) {
            float m0 = 0.f, m1 = 0.f;
            #pragma unroll
            for (int j4 = 0; j4 < 4; j4++) {
                float4 aq = scr4[i2 * 4 + j4];   // broadcast attn row chunk
                m0 = fmaf(aq.x, acc0[j4 * 4 + 0], fmaf(aq.y, acc0[j4 * 4 + 1],
                     fmaf(aq.z, acc0[j4 * 4 + 2], fmaf(aq.w, acc0[j4 * 4 + 3], m0))));
                m1 = fmaf(aq.x, acc1[j4 * 4 + 0], fmaf(aq.y, acc1[j4 * 4 + 1],
                     fmaf(aq.z, acc1[j4 * 4 + 2], fmaf(aq.w, acc1[j4 * 4 + 3], m1))));
            }
            m0 = (m0 > 0.f) ? m0 : (__expf(m0) - 1.f);   // elu
            m1 = (m1 > 0.f) ? m1 : (__expf(m1) - 1.f);
            pool0 = fmaxf(pool0, m0);
            pool1 = fmaxf(pool1, m1);
        }

        // ---- GRU: gx = x@Wx + b (transposed weights, float4 over input dim) ----
        for (int i = lane; i < 40; i += 32) scr[256 + i] = xf[(size_t)node * 40 + i];
        scr[512 + lane] = pool0;
        scr[544 + lane] = pool1;
        __syncwarp();

        float gx[6], gh[6];
        #pragma unroll
        for (int m = 0; m < 6; m++) { gx[m] = sB[lane + 32 * m]; gh[m] = 0.f; }

        #pragma unroll 1
        for (int dq = 0; dq < 10; dq++) {                  // 40 input dims, 4 per step
            float4 xv = *(const float4*)(scr + 256 + dq * 4);   // broadcast
            #pragma unroll
            for (int m = 0; m < 6; m++) {
                float4 w = *(const float4*)(sWxT + (lane + 32 * m) * 44 + dq * 4);
                gx[m] = fmaf(xv.x, w.x, fmaf(xv.y, w.y,
                        fmaf(xv.z, w.z, fmaf(xv.w, w.w, gx[m]))));
            }
        }
        #pragma unroll 1
        for (int kq = 0; kq < 16; kq++) {                  // 64 hidden dims, 4 per step
            float4 pv = *(const float4*)(scr + 512 + kq * 4);   // broadcast
            #pragma unroll
            for (int m = 0; m < 6; m++) {
                float4 w = *(const float4*)(sWhgT + (lane + 32 * m) * 68 + kq * 4);
                gh[m] = fmaf(pv.x, w.x, fmaf(pv.y, w.y,
                        fmaf(pv.z, w.z, fmaf(pv.w, w.w, gh[m]))));
            }
        }

        float z0 = 1.f / (1.f + __expf(-(gx[0] + gh[0])));
        float z1 = 1.f / (1.f + __expf(-(gx[1] + gh[1])));
        float r0 = 1.f / (1.f + __expf(-(gx[2] + gh[2])));
        float r1 = 1.f / (1.f + __expf(-(gx[3] + gh[3])));
        float n0 = tanhf(fmaf(r0, gh[4], gx[4]));
        float n1 = tanhf(fmaf(r1, gh[5], gx[5]));

        out[(size_t)node * 64 + lane]      = (1.f - z0) * n0 + z0 * pool0;
        out[(size_t)node * 64 + lane + 32] = (1.f - z1) * n1 + z1 * pool1;

        __syncwarp();  // scratch reuse safety across node iterations
    }
}

extern "C" void kernel_launch(void* const* d_in, const int* in_sizes, int n_in,
                              void* d_out, int out_size) {
    const float* node_features = (const float*)d_in[0];
    const float* child_hiddens = (const float*)d_in[1];
    const float* A_c           = (const float*)d_in[2];
    const int*   child_count   = (const int*)  d_in[3];
    const float* W             = (const float*)d_in[4];
    const float* a_src         = (const float*)d_in[5];
    const float* a_dst         = (const float*)d_in[6];
    const float* Wx            = (const float*)d_in[7];
    const float* Wh_g          = (const float*)d_in[8];
    const float* b             = (const float*)d_in[9];
    float* out = (float*)d_out;
    const int N = in_sizes[3];

    int dev = 0;
    cudaGetDevice(&dev);
    int sms = 148;
    cudaDeviceGetAttribute(&sms, cudaDevAttrMultiProcessorCount, dev);

    const size_t smem_bytes = (size_t)SMEM_FLOATS * sizeof(float);
    cudaFuncSetAttribute(rann_kernel, cudaFuncAttributeMaxDynamicSharedMemorySize,
                         (int)smem_bytes);

    rann_kernel<<<sms, THREADS, smem_bytes>>>(node_features, child_hiddens, A_c,
                                              child_count, W, a_src, a_dst,
                                              Wx, Wh_g, b, out, N);
}

// round 14
// speedup vs baseline: 1.3132x; 1.1822x over previous
#include <cuda_runtime.h>
#include <math.h>

// Problem constants
#define NNEG (-1e9f)
constexpr int THREADS = 512;
constexpr int WARPS   = THREADS / 32;
constexpr int NB      = 4;      // nodes batched per warp for the GRU pass

// Shared memory layout (float offsets)
constexpr int OFF_W    = 0;                 // W row-major 64*64 = 4096
constexpr int OFF_U    = OFF_W + 4096;      // u = W@a_src [64]
constexpr int OFF_V    = OFF_U + 64;        // v = W@a_dst [64]
constexpr int OFF_WXT  = OFF_V + 64;        // Wx^T  [192 cols][44] = 8448
constexpr int OFF_WHGT = OFF_WXT + 8448;    // Whg^T [192 cols][68] = 13056
constexpr int OFF_B    = OFF_WHGT + 13056;  // 192
constexpr int OFF_SCR  = OFF_B + 192;       // 25920
// per-warp scratch: ch/attn [0,1024), dst [1024,1040),
// x batch [1056,1232) (4x44), pooled batch [1232,1488) (4x64)
constexpr int SCR_PER_WARP = 1504;
constexpr int SMEM_FLOATS = OFF_SCR + WARPS * SCR_PER_WARP;  // 49984 floats = 199936 B

__global__ __launch_bounds__(THREADS, 1)
void rann_kernel(const float* __restrict__ xf,       // [N,40]
                 const float* __restrict__ ch,       // [N,16,64]
                 const float* __restrict__ Ac,       // [N,16,16]
                 const int*   __restrict__ ccnt,     // [N]
                 const float* __restrict__ gW,       // [64,64]
                 const float* __restrict__ gAs,      // [64]
                 const float* __restrict__ gAd,      // [64]
                 const float* __restrict__ gWx,      // [40,192]
                 const float* __restrict__ gWhg,     // [64,192]
                 const float* __restrict__ gB,       // [192]
                 float* __restrict__ out,            // [N,64]
                 int N)
{
    extern __shared__ float sm[];
    float* sW    = sm + OFF_W;
    float* sU    = sm + OFF_U;
    float* sV    = sm + OFF_V;
    float* sWxT  = sm + OFF_WXT;
    float* sWhgT = sm + OFF_WHGT;
    float* sB    = sm + OFF_B;

    const int tid = threadIdx.x;

    // Stage weights into shared once per block (persistent block)
    for (int i = tid; i < 4096;  i += THREADS) sW[i] = gW[i];
    for (int i = tid; i < 7680;  i += THREADS) {           // Wx^T[col][d], stride 44
        int d = i / 192, col = i % 192;
        sWxT[col * 44 + d] = gWx[i];
    }
    for (int i = tid; i < 12288; i += THREADS) {           // Whg^T[col][k], stride 68
        int k = i / 192, col = i % 192;
        sWhgT[col * 68 + k] = gWhg[i];
    }
    if (tid < 128) {                                       // u = W@a_src, v = W@a_dst
        const float* av = (tid < 64) ? gAs : gAd;
        int h = tid & 63;
        float s = 0.f;
        #pragma unroll 8
        for (int k = 0; k < 64; k++) s = fmaf(gW[h * 64 + k], av[k], s);
        ((tid < 64) ? sU : sV)[h] = s;
    }
    if (tid < 192) sB[tid] = gB[tid];
    __syncthreads();

    const int warp = tid >> 5;
    const int lane = tid & 31;
    float* scr  = sm + OFF_SCR + warp * SCR_PER_WARP;
    float4* scr4 = (float4*)scr;
    float* scrD = scr + 1024;                    // dst[16]
    float* scrX = scr + 1056;                    // x batch [NB][44]
    float* scrP = scr + 1232;                    // pooled batch [NB][64]

    const int gw_id = blockIdx.x * WARPS + warp;
    const int gw_n  = gridDim.x * WARPS;

    for (int base = gw_id * NB; base < N; base += gw_n * NB) {
        const int nv = min(NB, N - base);

        // ============ per-node attention + pool phase ============
        #pragma unroll 1
        for (int s = 0; s < nv; s++) {
            const int node = base + s;

            // ---- Load child_hiddens tile [16][64] into per-warp scratch ----
            const float4* chg = (const float4*)(ch + (size_t)node * 1024);
            #pragma unroll
            for (int i = 0; i < 8; i++) scr4[lane + 32 * i] = chg[lane + 32 * i];
            // ---- stage x row (40 floats) for the batched GRU ----
            if (lane < 10)
                *(float4*)(scrX + s * 44 + lane * 4) =
                    *(const float4*)(xf + (size_t)node * 40 + lane * 4);
            __syncwarp();

            // ---- Wh = ch @ W : lane holds columns k = lane, lane+32 ----
            float acc0[16], acc1[16];
            #pragma unroll
            for (int c = 0; c < 16; c++) { acc0[c] = 0.f; acc1[c] = 0.f; }

            #pragma unroll 1
            for (int h4 = 0; h4 < 16; h4++) {
                const int h = h4 * 4;
                float w0x = sW[(h + 0) * 64 + lane];
                float w0y = sW[(h + 1) * 64 + lane];
                float w0z = sW[(h + 2) * 64 + lane];
                float w0w = sW[(h + 3) * 64 + lane];
                float w1x = sW[(h + 0) * 64 + lane + 32];
                float w1y = sW[(h + 1) * 64 + lane + 32];
                float w1z = sW[(h + 2) * 64 + lane + 32];
                float w1w = sW[(h + 3) * 64 + lane + 32];
                #pragma unroll
                for (int c = 0; c < 16; c++) {
                    float4 q = scr4[c * 16 + h4];   // broadcast
                    acc0[c] = fmaf(q.x, w0x, fmaf(q.y, w0y, fmaf(q.z, w0z, fmaf(q.w, w0w, acc0[c]))));
                    acc1[c] = fmaf(q.x, w1x, fmaf(q.y, w1y, fmaf(q.z, w1z, fmaf(q.w, w1w, acc1[c]))));
                }
            }

            const int cc = ccnt[node];
            const int ai = lane >> 1;            // attention row for this lane pair
            const int half = lane & 1;

            // ---- src[ai], dst[ai] via u,v: src[c] = sum_h ch[c][h]*u[h] ----
            {
                const float4* chrow = (const float4*)(scr + ai * 64 + half * 32);
                const float4* up    = (const float4*)(sU + half * 32);
                const float4* vp    = (const float4*)(sV + half * 32);
                float su = 0.f, sv = 0.f;
                #pragma unroll
                for (int q = 0; q < 8; q++) {
                    float4 t = chrow[q], uq = up[q], vq = vp[q];
                    su = fmaf(t.x, uq.x, fmaf(t.y, uq.y, fmaf(t.z, uq.z, fmaf(t.w, uq.w, su))));
                    sv = fmaf(t.x, vq.x, fmaf(t.y, vq.y, fmaf(t.z, vq.z, fmaf(t.w, vq.w, sv))));
                }
                su += __shfl_xor_sync(0xffffffffu, su, 1);
                sv += __shfl_xor_sync(0xffffffffu, sv, 1);
                if (!half) scrD[ai] = sv;        // publish dst[c] for column reads
                __syncwarp();

                // ---- Attention row softmax: row ai, j in [jb, jb+8) ----
                const int jb = half * 8;
                const float* Arow = Ac + (size_t)node * 256 + ai * 16 + jb;
                float4 Aq0 = *(const float4*)(Arow);
                float4 Aq1 = *(const float4*)(Arow + 4);
                float av8[8] = {Aq0.x, Aq0.y, Aq0.z, Aq0.w, Aq1.x, Aq1.y, Aq1.z, Aq1.w};
                float4 d0 = *(const float4*)(scrD + jb);
                float4 d1 = *(const float4*)(scrD + jb + 4);
                float dv8[8] = {d0.x, d0.y, d0.z, d0.w, d1.x, d1.y, d1.z, d1.w};
                const bool vi = ai < cc;
                float ev[8];
                #pragma unroll
                for (int jj = 0; jj < 8; jj++) {
                    int j = jb + jj;
                    bool m = vi && (j < cc) && (av8[jj] > 0.5f);
                    float e = su + dv8[jj];
                    e = (e >= 0.f) ? e : 0.2f * e;       // leaky_relu 0.2
                    ev[jj] = m ? e : NNEG;
                }
                float mx = ev[0];
                #pragma unroll
                for (int jj = 1; jj < 8; jj++) mx = fmaxf(mx, ev[jj]);
                mx = fmaxf(mx, __shfl_xor_sync(0xffffffffu, mx, 1));
                float p[8], ssum = 0.f;
                #pragma unroll
                for (int jj = 0; jj < 8; jj++) { p[jj] = __expf(ev[jj] - mx); ssum += p[jj]; }
                ssum += __shfl_xor_sync(0xffffffffu, ssum, 1);
                float inv = 1.f / ssum;

                __syncwarp();  // all ch-tile reads done before attn overwrites scratch
                #pragma unroll
                for (int jj = 0; jj < 8; jj++) scr[ai * 16 + jb + jj] = p[jj] * inv;
                __syncwarp();
            }

            // ---- h_msg[i] = attn[i] @ Wh ; elu ; masked maxpool ----
            float pool0 = NNEG, pool1 = NNEG;
            #pragma unroll 1
            for (int i2 = 0; i2 < cc; i2++) {
                float m0 = 0.f, m1 = 0.f;
                #pragma unroll
                for (int j4 = 0; j4 < 4; j4++) {
                    float4 aq = scr4[i2 * 4 + j4];   // broadcast attn row chunk
                    m0 = fmaf(aq.x, acc0[j4 * 4 + 0], fmaf(aq.y, acc0[j4 * 4 + 1],
                         fmaf(aq.z, acc0[j4 * 4 + 2], fmaf(aq.w, acc0[j4 * 4 + 3], m0))));
                    m1 = fmaf(aq.x, acc1[j4 * 4 + 0], fmaf(aq.y, acc1[j4 * 4 + 1],
                         fmaf(aq.z, acc1[j4 * 4 + 2], fmaf(aq.w, acc1[j4 * 4 + 3], m1))));
                }
                m0 = (m0 > 0.f) ? m0 : (__expf(m0) - 1.f);   // elu
                m1 = (m1 > 0.f) ? m1 : (__expf(m1) - 1.f);
                pool0 = fmaxf(pool0, m0);
                pool1 = fmaxf(pool1, m1);
            }
            scrP[s * 64 + lane]      = pool0;
            scrP[s * 64 + lane + 32] = pool1;
            __syncwarp();   // pool reads of attn done before next node restages ch
        }

        // ============ batched GRU for NB nodes (weight reads amortized 4x) ============
        float gx[NB][6], gh[NB][6];
        #pragma unroll
        for (int s = 0; s < NB; s++)
            #pragma unroll
            for (int m = 0; m < 6; m++) { gx[s][m] = 0.f; gh[s][m] = 0.f; }

        #pragma unroll 1
        for (int dq = 0; dq < 10; dq++) {                  // 40 input dims, 4 per step
            float4 xq[NB];
            #pragma unroll
            for (int s = 0; s < NB; s++)
                xq[s] = *(const float4*)(scrX + s * 44 + dq * 4);   // broadcast
            #pragma unroll
            for (int m = 0; m < 6; m++) {
                float4 w = *(const float4*)(sWxT + (lane + 32 * m) * 44 + dq * 4);
                #pragma unroll
                for (int s = 0; s < NB; s++) {
                    gx[s][m] = fmaf(xq[s].x, w.x, fmaf(xq[s].y, w.y,
                               fmaf(xq[s].z, w.z, fmaf(xq[s].w, w.w, gx[s][m]))));
                }
            }
        }
        #pragma unroll 1
        for (int kq = 0; kq < 16; kq++) {                  // 64 hidden dims, 4 per step
            float4 pq[NB];
            #pragma unroll
            for (int s = 0; s < NB; s++)
                pq[s] = *(const float4*)(scrP + s * 64 + kq * 4);   // broadcast
            #pragma unroll
            for (int m = 0; m < 6; m++) {
                float4 w = *(const float4*)(sWhgT + (lane + 32 * m) * 68 + kq * 4);
                #pragma unroll
                for (int s = 0; s < NB; s++) {
                    gh[s][m] = fmaf(pq[s].x, w.x, fmaf(pq[s].y, w.y,
                               fmaf(pq[s].z, w.z, fmaf(pq[s].w, w.w, gh[s][m]))));
                }
            }
        }

        #pragma unroll
        for (int s = 0; s < NB; s++) {
            if (base + s >= N) break;
            float z0 = 1.f / (1.f + __expf(-(gx[s][0] + sB[lane]       + gh[s][0])));
            float z1 = 1.f / (1.f + __expf(-(gx[s][1] + sB[lane + 32]  + gh[s][1])));
            float r0 = 1.f / (1.f + __expf(-(gx[s][2] + sB[lane + 64]  + gh[s][2])));
            float r1 = 1.f / (1.f + __expf(-(gx[s][3] + sB[lane + 96]  + gh[s][3])));
            float n0 = tanhf(fmaf(r0, gh[s][4], gx[s][4] + sB[lane + 128]));
            float n1 = tanhf(fmaf(r1, gh[s][5], gx[s][5] + sB[lane + 160]));

            float pool0 = scrP[s * 64 + lane];
            float pool1 = scrP[s * 64 + lane + 32];
            out[(size_t)(base + s) * 64 + lane]      = (1.f - z0) * n0 + z0 * pool0;
            out[(size_t)(base + s) * 64 + lane + 32] = (1.f - z1) * n1 + z1 * pool1;
        }
        __syncwarp();  // scratch reuse safety across batch iterations
    }
}

extern "C" void kernel_launch(void* const* d_in, const int* in_sizes, int n_in,
                              void* d_out, int out_size) {
    const float* node_features = (const float*)d_in[0];
    const float* child_hiddens = (const float*)d_in[1];
    const float* A_c           = (const float*)d_in[2];
    const int*   child_count   = (const int*)  d_in[3];
    const float* W             = (const float*)d_in[4];
    const float* a_src         = (const float*)d_in[5];
    const float* a_dst         = (const float*)d_in[6];
    const float* Wx            = (const float*)d_in[7];
    const float* Wh_g          = (const float*)d_in[8];
    const float* b             = (const float*)d_in[9];
    float* out = (float*)d_out;
    const int N = in_sizes[3];

    int dev = 0;
    cudaGetDevice(&dev);
    int sms = 148;
    cudaDeviceGetAttribute(&sms, cudaDevAttrMultiProcessorCount, dev);

    const size_t smem_bytes = (size_t)SMEM_FLOATS * sizeof(float);
    cudaFuncSetAttribute(rann_kernel, cudaFuncAttributeMaxDynamicSharedMemorySize,
                         (int)smem_bytes);

    rann_kernel<<<sms, THREADS, smem_bytes>>>(node_features, child_hiddens, A_c,
                                              child_count, W, a_src, a_dst,
                                              Wx, Wh_g, b, out, N);
}